// round 15
// baseline (speedup 1.0000x reference)
#include <cuda_runtime.h>
#include <cuda_fp16.h>
#include <math.h>
#include <stdint.h>

// Problem constants
#define BATCH 4
#define TSEQ 2048
#define DMODEL 1024
#define NHEAD 16
#define DHEAD 64
#define DFF 4096
#define MROWS (BATCH * TSEQ)   // 8192

// ---------------------------------------------------------------------------
// Scratch (device globals; no runtime allocation allowed)
// ---------------------------------------------------------------------------
__device__ float  g_x1[(size_t)MROWS * DMODEL];
__device__ __half g_qkvh[(size_t)MROWS * 3 * DMODEL];
__device__ __half g_act[(size_t)MROWS * DMODEL];
__device__ __half g_ff[(size_t)MROWS * DFF];
__device__ __half g_wqkv[(size_t)3 * DMODEL * DMODEL];
__device__ __half g_wout[(size_t)DMODEL * DMODEL];
__device__ __half g_wfc1[(size_t)DFF * DMODEL];
__device__ __half g_wfc2[(size_t)DMODEL * DFF];

// ---------------------------------------------------------------------------
// Helpers
// ---------------------------------------------------------------------------
__device__ __forceinline__ uint32_t smem_u32(const void* p) {
    uint32_t a;
    asm("{ .reg .u64 t; cvta.to.shared.u64 t, %1; cvt.u32.u64 %0, t; }"
        : "=r"(a) : "l"(p));
    return a;
}

__device__ __forceinline__ float ex2f(float x) {   // raw MUFU.EX2
    float r;
    asm("ex2.approx.f32 %0, %1;" : "=f"(r) : "f"(x));
    return r;
}

#define LDSM_X4(d, a)                                                        \
    asm volatile("ldmatrix.sync.aligned.m8n8.x4.shared.b16 "                 \
                 "{%0,%1,%2,%3}, [%4];"                                      \
                 : "=r"((d)[0]), "=r"((d)[1]), "=r"((d)[2]), "=r"((d)[3])    \
                 : "r"(a))

#define LDSM_X4_T(d, a)                                                      \
    asm volatile("ldmatrix.sync.aligned.m8n8.x4.trans.shared.b16 "           \
                 "{%0,%1,%2,%3}, [%4];"                                      \
                 : "=r"((d)[0]), "=r"((d)[1]), "=r"((d)[2]), "=r"((d)[3])    \
                 : "r"(a))

#define MMA16816(c, a, b0, b1)                                               \
    asm volatile("mma.sync.aligned.m16n8k16.row.col.f32.f16.f16.f32 "        \
                 "{%0,%1,%2,%3},{%4,%5,%6,%7},{%8,%9},{%0,%1,%2,%3};"        \
                 : "+f"((c)[0]), "+f"((c)[1]), "+f"((c)[2]), "+f"((c)[3])    \
                 : "r"((a)[0]), "r"((a)[1]), "r"((a)[2]), "r"((a)[3]),       \
                   "r"(b0), "r"(b1))

#define CP_ASYNC16(s, g) \
    asm volatile("cp.async.cg.shared.global [%0], [%1], 16;" :: "r"(s), "l"(g))
#define CP_COMMIT() asm volatile("cp.async.commit_group;")
#define CP_WAIT1()  asm volatile("cp.async.wait_group 1;")

__device__ __forceinline__ float gelu_exact(float x) {
    return 0.5f * x * (1.0f + erff(x * 0.70710678118654752f));
}

// Q pre-scale: (1/sqrt(64)) * log2(e) so softmax runs in exp2 domain
#define QKSCALE 0.18033688011112042f

// ---------------------------------------------------------------------------
// Fused weight convert: all four weight tensors in ONE launch.
// ---------------------------------------------------------------------------
#define N4_WQ (3 * DMODEL * DMODEL / 4)
#define N4_WO (DMODEL * DMODEL / 4)
#define N4_W1 (DFF * DMODEL / 4)
#define N4_W2 (DMODEL * DFF / 4)
#define N4_TOTAL (N4_WQ + N4_WO + N4_W1 + N4_W2)

__global__ __launch_bounds__(256)
void cvt4_kernel(const float* __restrict__ wq_in, const float* __restrict__ wo_in,
                 const float* __restrict__ w1_in, const float* __restrict__ w2_in,
                 __half* __restrict__ wq, __half* __restrict__ wo,
                 __half* __restrict__ w1, __half* __restrict__ w2) {
    int i = blockIdx.x * 256 + threadIdx.x;
    const float* in;
    __half* out;
    if (i < N4_WQ)                       { in = wq_in; out = wq; }
    else if ((i -= N4_WQ) < N4_WO)       { in = wo_in; out = wo; }
    else if ((i -= N4_WO) < N4_W1)       { in = w1_in; out = w1; }
    else { i -= N4_W1;                     in = w2_in; out = w2; }
    const float4 v = ((const float4*)in)[i];
    ((__half2*)out)[i * 2 + 0] = __floats2half2_rn(v.x, v.y);
    ((__half2*)out)[i * 2 + 1] = __floats2half2_rn(v.z, v.w);
}

// ---------------------------------------------------------------------------
// LayerNorm -> single fp16
// ---------------------------------------------------------------------------
__global__ __launch_bounds__(256)
void ln_kernel(const float* __restrict__ x, const float* __restrict__ sc,
               const float* __restrict__ bi, __half* __restrict__ y) {
    const int row = blockIdx.x;
    const int t = threadIdx.x;
    const float4 v = *(const float4*)(x + (size_t)row * DMODEL + t * 4);
    float s = v.x + v.y + v.z + v.w;
    float s2 = v.x * v.x + v.y * v.y + v.z * v.z + v.w * v.w;
#pragma unroll
    for (int o = 16; o; o >>= 1) {
        s  += __shfl_xor_sync(0xffffffffu, s, o);
        s2 += __shfl_xor_sync(0xffffffffu, s2, o);
    }
    __shared__ float rs[8], rs2[8];
    if ((t & 31) == 0) { rs[t >> 5] = s; rs2[t >> 5] = s2; }
    __syncthreads();
    s = 0.f; s2 = 0.f;
#pragma unroll
    for (int i = 0; i < 8; i++) { s += rs[i]; s2 += rs2[i]; }
    const float mu = s * (1.0f / DMODEL);
    const float var = s2 * (1.0f / DMODEL) - mu * mu;
    const float r = rsqrtf(var + 1e-5f);
    const float4 g4 = *(const float4*)(sc + t * 4);
    const float4 b4 = *(const float4*)(bi + t * 4);
    float4 o4;
    o4.x = (v.x - mu) * r * g4.x + b4.x;
    o4.y = (v.y - mu) * r * g4.y + b4.y;
    o4.z = (v.z - mu) * r * g4.z + b4.z;
    o4.w = (v.w - mu) * r * g4.w + b4.w;
    const size_t off = (size_t)row * DMODEL + t * 4;
    ((__half2*)(y + off))[0] = __floats2half2_rn(o4.x, o4.y);
    ((__half2*)(y + off))[1] = __floats2half2_rn(o4.z, o4.w);
}

// ---------------------------------------------------------------------------
// HMMA fp16 GEMM (R14 measured-best, unchanged): C = A @ W^T, fp32 accum.
//   EPI 0: none | 1: +res | 2: +bias,GELU | 3: +bias+res
//   OUTMODE 0: fp32 C | 2: single fp16 Ch
//   QSCALE 1: multiply cols [0,1024) by QKSCALE before store
// CTA tile 128x256, 512 threads = 16 warps (4x4), warp tile 32x64, BK=64,
// 3-stage cp.async ring, one barrier per k-tile.
// ---------------------------------------------------------------------------
#define GH_ROWB  144
#define GH_A_ARR (128 * GH_ROWB)
#define GH_B_ARR (256 * GH_ROWB)
#define GH_STAGE (GH_A_ARR + GH_B_ARR)     // 55296
#define GH_SMEM  (3 * GH_STAGE)            // 165888

template <int EPI, int OUTMODE, int QSCALE>
__global__ __launch_bounds__(512, 1)
void gemm_hmma(const __half* __restrict__ Ah, const __half* __restrict__ Bh,
               float* __restrict__ C, __half* __restrict__ Ch,
               int M, int N, int K,
               const float* __restrict__ bias, const float* __restrict__ res) {
    extern __shared__ char sm[];
    const uint32_t sb = smem_u32(sm);
    const int tid = threadIdx.x;
    const int lane = tid & 31, wid = tid >> 5;
    const int warp_m = wid >> 2, warp_n = wid & 3;   // 4 x 4
    const int bm = blockIdx.y * 128, bn = blockIdx.x * 256;
    const int NT = K >> 6;   // K tiles of 64

    auto load_stage = [&](int st, int kt) {
        const int k0 = kt * 64;
        const uint32_t so = sb + st * GH_STAGE;
#pragma unroll
        for (int i = 0; i < 2; i++) {                 // A: 128 rows x 8 kc
            const int idx = tid + i * 512;
            const int r = idx >> 3, kc = idx & 7;
            CP_ASYNC16(so + r * GH_ROWB + kc * 16,
                       Ah + (size_t)(bm + r) * K + k0 + kc * 8);
        }
#pragma unroll
        for (int i = 0; i < 4; i++) {                 // B: 256 rows x 8 kc
            const int idx = tid + i * 512;
            const int r = idx >> 3, kc = idx & 7;
            CP_ASYNC16(so + GH_A_ARR + r * GH_ROWB + kc * 16,
                       Bh + (size_t)(bn + r) * K + k0 + kc * 8);
        }
    };

    load_stage(0, 0); CP_COMMIT();

    float acc[2][8][4];
#pragma unroll
    for (int a = 0; a < 2; a++)
#pragma unroll
        for (int b = 0; b < 8; b++)
#pragma unroll
            for (int c = 0; c < 4; c++) acc[a][b][c] = 0.f;

    for (int kt = 0; kt < NT; kt++) {
        if (kt + 1 < NT) load_stage((kt + 1) % 3, kt + 1);
        CP_COMMIT();
        CP_WAIT1();
        __syncthreads();

        const uint32_t s0 = sb + (kt % 3) * GH_STAGE;
#pragma unroll
        for (int kh = 0; kh < 4; kh++) {
            uint32_t a_f[2][4], b_f[4][4];
#pragma unroll
            for (int mt = 0; mt < 2; mt++) {
                const int row = warp_m * 32 + mt * 16 + (lane & 15);
                LDSM_X4(a_f[mt], s0 + row * GH_ROWB + kh * 32 + (lane >> 4) * 16);
            }
#pragma unroll
            for (int nt = 0; nt < 4; nt++) {
                const int row = warp_n * 64 + nt * 16 + (lane & 7) + ((lane >> 4) << 3);
                LDSM_X4(b_f[nt], s0 + GH_A_ARR + row * GH_ROWB + kh * 32 +
                                 ((lane >> 3) & 1) * 16);
            }
#pragma unroll
            for (int mt = 0; mt < 2; mt++)
#pragma unroll
                for (int j = 0; j < 8; j++)
                    MMA16816(acc[mt][j], a_f[mt],
                             b_f[j >> 1][(j & 1) * 2], b_f[j >> 1][(j & 1) * 2 + 1]);
        }
    }

    const int gq = lane >> 2, tq = lane & 3;
#pragma unroll
    for (int mt = 0; mt < 2; mt++) {
#pragma unroll
        for (int j = 0; j < 8; j++) {
            const int col = bn + warp_n * 64 + j * 8 + tq * 2;
            float2 bb = make_float2(0.f, 0.f);
            if (EPI == 2 || EPI == 3) bb = *(const float2*)&bias[col];
#pragma unroll
            for (int rr = 0; rr < 2; rr++) {
                const int row = bm + warp_m * 32 + mt * 16 + gq + rr * 8;
                float vx = acc[mt][j][rr * 2 + 0];
                float vy = acc[mt][j][rr * 2 + 1];
                if (EPI == 2 || EPI == 3) { vx += bb.x; vy += bb.y; }
                if (EPI == 2) { vx = gelu_exact(vx); vy = gelu_exact(vy); }
                if (EPI == 1 || EPI == 3) {
                    const float2 rv = *(const float2*)&res[(size_t)row * N + col];
                    vx += rv.x; vy += rv.y;
                }
                if (QSCALE && col < DMODEL) { vx *= QKSCALE; vy *= QKSCALE; }
                if (OUTMODE == 2) {
                    *(__half2*)&Ch[(size_t)row * N + col] = __floats2half2_rn(vx, vy);
                } else {
                    *(float2*)&C[(size_t)row * N + col] = make_float2(vx, vy);
                }
            }
        }
    }
}

// ---------------------------------------------------------------------------
// HMMA flash attention, 16 warps/SM version.
// Grid (T/128, H, B), 256 threads = 8 warps; each warp owns 16 q-rows.
// Q pre-scaled by log2e/sqrt(dh) -> softmax in exp2 domain.
// K/V 64x64 tiles, 3-stage cp.async ring, prefetch distance 2,
// one barrier per kv-tile. 2 CTAs/SM (regs capped at 128).
// Softmax sum-reduce deferred to epilogue (per-lane partial l).
// ---------------------------------------------------------------------------
#define AQ_S 72
#define ATT_Q     0
#define ATT_K(s)  (9216 + (s) * 4608)
#define ATT_V(s)  (23040 + (s) * 4608)
#define ATT_SMEM  (36864 * 2)          // 73728 B

__global__ __launch_bounds__(256, 2)
void attn_hmma(const __half* __restrict__ qkv, __half* __restrict__ ao) {
    extern __shared__ __half sh[];
    const uint32_t sb = smem_u32(sh);
    const int tid = threadIdx.x;
    const int lane = tid & 31, w = tid >> 5;
    const int b = blockIdx.z, h = blockIdx.y, qt = blockIdx.x;
    const int hoff = h * DHEAD;
    const int rowbase = b * TSEQ + qt * 128;

    // Load Q tile (128 rows x 64 halfs), 256 threads
#pragma unroll
    for (int p = 0; p < 4; p++) {
        const int idx = tid + p * 256;
        const int r = idx >> 3, c8 = idx & 7;
        *(uint4*)(sh + ATT_Q + r * AQ_S + c8 * 8) =
            *(const uint4*)(qkv + (size_t)(rowbase + r) * 3072 + hoff + c8 * 8);
    }

    auto load_kv = [&](int st, int kt) {
        const int kvbase = b * TSEQ + kt * 64;
#pragma unroll
        for (int p = 0; p < 2; p++) {
            const int idx = tid + p * 256;
            const int r = idx >> 3, c8 = idx & 7;
            const __half* gk = qkv + (size_t)(kvbase + r) * 3072 + 1024 + hoff + c8 * 8;
            CP_ASYNC16(sb + 2 * (ATT_K(st) + r * AQ_S + c8 * 8), gk);
            CP_ASYNC16(sb + 2 * (ATT_V(st) + r * AQ_S + c8 * 8), gk + 1024);
        }
    };

    load_kv(0, 0); CP_COMMIT();
    load_kv(1, 1); CP_COMMIT();
    __syncthreads();   // Q visibility (plain stores) before ldsm preload

    // Preload Q A-fragments: 1 row-group (16 rows) x 4 k-steps
    uint32_t qa[4][4];
    const int m0 = w * 16;
#pragma unroll
    for (int kk = 0; kk < 4; kk++) {
        const uint32_t ad = sb + 2 * (ATT_Q + (m0 + (lane & 15)) * AQ_S +
                                      kk * 16 + (lane >> 4) * 8);
        LDSM_X4(qa[kk], ad);
    }

    float m0_ = -1e30f, m1_ = -1e30f;
    float l0_ = 0.f, l1_ = 0.f;      // per-lane partial sums (reduced at end)
    float o[8][4];
#pragma unroll
    for (int n = 0; n < 8; n++)
#pragma unroll
        for (int j = 0; j < 4; j++) o[n][j] = 0.f;

    const int NT = TSEQ / 64;
    for (int kt = 0; kt < NT; kt++) {
        CP_WAIT1();
        __syncthreads();
        if (kt + 2 < NT) load_kv((kt + 2) % 3, kt + 2);
        CP_COMMIT();
        const int s = kt % 3;

        // ---- S = Q K^T (log2-domain scores) ----
        float c[8][4];
#pragma unroll
        for (int n = 0; n < 8; n++)
#pragma unroll
            for (int j = 0; j < 4; j++) c[n][j] = 0.f;

#pragma unroll
        for (int kk2 = 0; kk2 < 2; kk2++) {
#pragma unroll
            for (int n = 0; n < 8; n++) {
                uint32_t bf[4];
                const uint32_t ad = sb + 2 * (ATT_K(s) + (n * 8 + (lane & 7)) * AQ_S +
                                              kk2 * 32 + (lane >> 3) * 8);
                LDSM_X4(bf, ad);
                MMA16816(c[n], qa[2 * kk2], bf[0], bf[1]);
                MMA16816(c[n], qa[2 * kk2 + 1], bf[2], bf[3]);
            }
        }

        // ---- online softmax (exp2 domain); sum reduce deferred ----
        float tm0 = -1e30f, tm1 = -1e30f;
#pragma unroll
        for (int n = 0; n < 8; n++) {
            tm0 = fmaxf(tm0, fmaxf(c[n][0], c[n][1]));
            tm1 = fmaxf(tm1, fmaxf(c[n][2], c[n][3]));
        }
#pragma unroll
        for (int ofs = 1; ofs <= 2; ofs <<= 1) {
            tm0 = fmaxf(tm0, __shfl_xor_sync(0xffffffffu, tm0, ofs));
            tm1 = fmaxf(tm1, __shfl_xor_sync(0xffffffffu, tm1, ofs));
        }
        const float mn0 = fmaxf(m0_, tm0), mn1 = fmaxf(m1_, tm1);
        const float al0 = ex2f(m0_ - mn0), al1 = ex2f(m1_ - mn1);
        m0_ = mn0; m1_ = mn1;

        uint32_t u01[8], u23[8];
        float rs0 = 0.f, rs1 = 0.f;
#pragma unroll
        for (int n = 0; n < 8; n++) {
            const float p0 = ex2f(c[n][0] - mn0);
            const float p1 = ex2f(c[n][1] - mn0);
            const float p2 = ex2f(c[n][2] - mn1);
            const float p3 = ex2f(c[n][3] - mn1);
            rs0 += p0 + p1; rs1 += p2 + p3;
            const __half2 h01 = __floats2half2_rn(p0, p1);
            const __half2 h23 = __floats2half2_rn(p2, p3);
            u01[n] = *(const uint32_t*)&h01;
            u23[n] = *(const uint32_t*)&h23;
        }
        l0_ = l0_ * al0 + rs0;   // per-lane partial; alpha is row-uniform
        l1_ = l1_ * al1 + rs1;
#pragma unroll
        for (int n = 0; n < 8; n++) {
            o[n][0] *= al0; o[n][1] *= al0;
            o[n][2] *= al1; o[n][3] *= al1;
        }

        // ---- O += P V ----
#pragma unroll
        for (int kk = 0; kk < 4; kk++) {
            uint32_t au[4] = {u01[2 * kk], u23[2 * kk],
                              u01[2 * kk + 1], u23[2 * kk + 1]};
#pragma unroll
            for (int n2 = 0; n2 < 4; n2++) {
                uint32_t bf[4];
                const uint32_t ad = sb + 2 * (ATT_V(s) + (kk * 16 + (lane & 15)) * AQ_S +
                                              n2 * 16 + (lane >> 4) * 8);
                LDSM_X4_T(bf, ad);
                MMA16816(o[2 * n2], au, bf[0], bf[1]);
                MMA16816(o[2 * n2 + 1], au, bf[2], bf[3]);
            }
        }
    }

    // ---- epilogue: reduce deferred l across the 4 lanes of each row ----
#pragma unroll
    for (int ofs = 1; ofs <= 2; ofs <<= 1) {
        l0_ += __shfl_xor_sync(0xffffffffu, l0_, ofs);
        l1_ += __shfl_xor_sync(0xffffffffu, l1_, ofs);
    }
    const float inv0 = 1.0f / l0_, inv1 = 1.0f / l1_;
    const int r0 = lane >> 2, tq = lane & 3;
    const int grow0 = rowbase + m0 + r0, grow1 = grow0 + 8;
#pragma unroll
    for (int n = 0; n < 8; n++) {
        const int col = hoff + n * 8 + tq * 2;
        *(__half2*)&ao[(size_t)grow0 * DMODEL + col] =
            __floats2half2_rn(o[n][0] * inv0, o[n][1] * inv0);
        *(__half2*)&ao[(size_t)grow1 * DMODEL + col] =
            __floats2half2_rn(o[n][2] * inv1, o[n][3] * inv1);
    }
}

// ---------------------------------------------------------------------------
// Launcher
// ---------------------------------------------------------------------------
extern "C" void kernel_launch(void* const* d_in, const int* in_sizes, int n_in,
                              void* d_out, int out_size) {
    const float* x     = (const float*)d_in[0];
    const float* ln1_s = (const float*)d_in[1];
    const float* ln1_b = (const float*)d_in[2];
    const float* qkv_w = (const float*)d_in[3];
    const float* out_w = (const float*)d_in[4];
    const float* ln2_s = (const float*)d_in[5];
    const float* ln2_b = (const float*)d_in[6];
    const float* fc1_w = (const float*)d_in[7];
    const float* fc1_b = (const float*)d_in[8];
    const float* fc2_w = (const float*)d_in[9];
    const float* fc2_b = (const float*)d_in[10];
    float* out = (float*)d_out;

    float *x1_p;
    __half *qkvh, *act, *ff, *wq, *wo, *w1, *w2;
    cudaGetSymbolAddress((void**)&x1_p, g_x1);
    cudaGetSymbolAddress((void**)&qkvh, g_qkvh);
    cudaGetSymbolAddress((void**)&act, g_act);
    cudaGetSymbolAddress((void**)&ff, g_ff);
    cudaGetSymbolAddress((void**)&wq, g_wqkv);
    cudaGetSymbolAddress((void**)&wo, g_wout);
    cudaGetSymbolAddress((void**)&w1, g_wfc1);
    cudaGetSymbolAddress((void**)&w2, g_wfc2);

    cudaFuncSetAttribute(gemm_hmma<0, 2, 1>, cudaFuncAttributeMaxDynamicSharedMemorySize, GH_SMEM);
    cudaFuncSetAttribute(gemm_hmma<1, 0, 0>, cudaFuncAttributeMaxDynamicSharedMemorySize, GH_SMEM);
    cudaFuncSetAttribute(gemm_hmma<2, 2, 0>, cudaFuncAttributeMaxDynamicSharedMemorySize, GH_SMEM);
    cudaFuncSetAttribute(gemm_hmma<3, 0, 0>, cudaFuncAttributeMaxDynamicSharedMemorySize, GH_SMEM);
    cudaFuncSetAttribute(attn_hmma, cudaFuncAttributeMaxDynamicSharedMemorySize, ATT_SMEM);

    // 0) Weight prep: all four fp32 -> fp16 in ONE launch
    cvt4_kernel<<<N4_TOTAL / 256, 256>>>(qkv_w, out_w, fc1_w, fc2_w, wq, wo, w1, w2);

    // 1) LN1 -> fp16 activations
    ln_kernel<<<MROWS, 256>>>(x, ln1_s, ln1_b, act);

    // 2) QKV projection -> fp16 (Q pre-scaled by log2e/8)
    gemm_hmma<0, 2, 1><<<dim3(3 * DMODEL / 256, MROWS / 128), 512, GH_SMEM>>>(
        act, wq, nullptr, qkvh, MROWS, 3 * DMODEL, DMODEL, nullptr, nullptr);

    // 3) HMMA flash attention -> fp16 (256 threads, 16 warps/SM)
    attn_hmma<<<dim3(TSEQ / 128, NHEAD, BATCH), 256, ATT_SMEM>>>(qkvh, act);

    // 4) Out projection + residual -> x1 fp32
    gemm_hmma<1, 0, 0><<<dim3(DMODEL / 256, MROWS / 128), 512, GH_SMEM>>>(
        act, wo, x1_p, nullptr, MROWS, DMODEL, DMODEL, nullptr, x);

    // 5) LN2 -> fp16 activations
    ln_kernel<<<MROWS, 256>>>(x1_p, ln2_s, ln2_b, act);

    // 6) FC1 + bias + GELU -> fp16
    gemm_hmma<2, 2, 0><<<dim3(DFF / 256, MROWS / 128), 512, GH_SMEM>>>(
        act, w1, nullptr, ff, MROWS, DFF, DMODEL, fc1_b, nullptr);

    // 7) FC2 + bias + residual -> out fp32
    gemm_hmma<3, 0, 0><<<dim3(DMODEL / 256, MROWS / 128), 512, GH_SMEM>>>(
        ff, w2, out, nullptr, MROWS, DMODEL, DFF, fc2_b, x1_p);
}

// round 16
// speedup vs baseline: 1.0166x; 1.0166x over previous
#include <cuda_runtime.h>
#include <cuda_fp16.h>
#include <math.h>
#include <stdint.h>

// Problem constants
#define BATCH 4
#define TSEQ 2048
#define DMODEL 1024
#define NHEAD 16
#define DHEAD 64
#define DFF 4096
#define MROWS (BATCH * TSEQ)   // 8192

// ---------------------------------------------------------------------------
// Scratch (device globals; no runtime allocation allowed)
// ---------------------------------------------------------------------------
__device__ float  g_x1[(size_t)MROWS * DMODEL];
__device__ __half g_qkvh[(size_t)MROWS * 3 * DMODEL];
__device__ __half g_act[(size_t)MROWS * DMODEL];
__device__ __half g_ff[(size_t)MROWS * DFF];
__device__ __half g_wqkv[(size_t)3 * DMODEL * DMODEL];
__device__ __half g_wout[(size_t)DMODEL * DMODEL];
__device__ __half g_wfc1[(size_t)DFF * DMODEL];
__device__ __half g_wfc2[(size_t)DMODEL * DFF];

// ---------------------------------------------------------------------------
// Helpers
// ---------------------------------------------------------------------------
__device__ __forceinline__ uint32_t smem_u32(const void* p) {
    uint32_t a;
    asm("{ .reg .u64 t; cvta.to.shared.u64 t, %1; cvt.u32.u64 %0, t; }"
        : "=r"(a) : "l"(p));
    return a;
}

__device__ __forceinline__ float ex2f(float x) {   // raw MUFU.EX2
    float r;
    asm("ex2.approx.f32 %0, %1;" : "=f"(r) : "f"(x));
    return r;
}

#define LDSM_X4(d, a)                                                        \
    asm volatile("ldmatrix.sync.aligned.m8n8.x4.shared.b16 "                 \
                 "{%0,%1,%2,%3}, [%4];"                                      \
                 : "=r"((d)[0]), "=r"((d)[1]), "=r"((d)[2]), "=r"((d)[3])    \
                 : "r"(a))

#define LDSM_X4_T(d, a)                                                      \
    asm volatile("ldmatrix.sync.aligned.m8n8.x4.trans.shared.b16 "           \
                 "{%0,%1,%2,%3}, [%4];"                                      \
                 : "=r"((d)[0]), "=r"((d)[1]), "=r"((d)[2]), "=r"((d)[3])    \
                 : "r"(a))

#define MMA16816(c, a, b0, b1)                                               \
    asm volatile("mma.sync.aligned.m16n8k16.row.col.f32.f16.f16.f32 "        \
                 "{%0,%1,%2,%3},{%4,%5,%6,%7},{%8,%9},{%0,%1,%2,%3};"        \
                 : "+f"((c)[0]), "+f"((c)[1]), "+f"((c)[2]), "+f"((c)[3])    \
                 : "r"((a)[0]), "r"((a)[1]), "r"((a)[2]), "r"((a)[3]),       \
                   "r"(b0), "r"(b1))

#define CP_ASYNC16(s, g) \
    asm volatile("cp.async.cg.shared.global [%0], [%1], 16;" :: "r"(s), "l"(g))
#define CP_COMMIT() asm volatile("cp.async.commit_group;")
#define CP_WAIT1()  asm volatile("cp.async.wait_group 1;")

__device__ __forceinline__ float gelu_exact(float x) {
    return 0.5f * x * (1.0f + erff(x * 0.70710678118654752f));
}

// Q pre-scale: (1/sqrt(64)) * log2(e) so softmax runs in exp2 domain
#define QKSCALE 0.18033688011112042f

// ---------------------------------------------------------------------------
// Fused weight convert: all four weight tensors in ONE launch.
// ---------------------------------------------------------------------------
#define N4_WQ (3 * DMODEL * DMODEL / 4)
#define N4_WO (DMODEL * DMODEL / 4)
#define N4_W1 (DFF * DMODEL / 4)
#define N4_W2 (DMODEL * DFF / 4)
#define N4_TOTAL (N4_WQ + N4_WO + N4_W1 + N4_W2)

__global__ __launch_bounds__(256)
void cvt4_kernel(const float* __restrict__ wq_in, const float* __restrict__ wo_in,
                 const float* __restrict__ w1_in, const float* __restrict__ w2_in,
                 __half* __restrict__ wq, __half* __restrict__ wo,
                 __half* __restrict__ w1, __half* __restrict__ w2) {
    int i = blockIdx.x * 256 + threadIdx.x;
    const float* in;
    __half* out;
    if (i < N4_WQ)                       { in = wq_in; out = wq; }
    else if ((i -= N4_WQ) < N4_WO)       { in = wo_in; out = wo; }
    else if ((i -= N4_WO) < N4_W1)       { in = w1_in; out = w1; }
    else { i -= N4_W1;                     in = w2_in; out = w2; }
    const float4 v = ((const float4*)in)[i];
    ((__half2*)out)[i * 2 + 0] = __floats2half2_rn(v.x, v.y);
    ((__half2*)out)[i * 2 + 1] = __floats2half2_rn(v.z, v.w);
}

// ---------------------------------------------------------------------------
// LayerNorm -> single fp16
// ---------------------------------------------------------------------------
__global__ __launch_bounds__(256)
void ln_kernel(const float* __restrict__ x, const float* __restrict__ sc,
               const float* __restrict__ bi, __half* __restrict__ y) {
    const int row = blockIdx.x;
    const int t = threadIdx.x;
    const float4 v = *(const float4*)(x + (size_t)row * DMODEL + t * 4);
    float s = v.x + v.y + v.z + v.w;
    float s2 = v.x * v.x + v.y * v.y + v.z * v.z + v.w * v.w;
#pragma unroll
    for (int o = 16; o; o >>= 1) {
        s  += __shfl_xor_sync(0xffffffffu, s, o);
        s2 += __shfl_xor_sync(0xffffffffu, s2, o);
    }
    __shared__ float rs[8], rs2[8];
    if ((t & 31) == 0) { rs[t >> 5] = s; rs2[t >> 5] = s2; }
    __syncthreads();
    s = 0.f; s2 = 0.f;
#pragma unroll
    for (int i = 0; i < 8; i++) { s += rs[i]; s2 += rs2[i]; }
    const float mu = s * (1.0f / DMODEL);
    const float var = s2 * (1.0f / DMODEL) - mu * mu;
    const float r = rsqrtf(var + 1e-5f);
    const float4 g4 = *(const float4*)(sc + t * 4);
    const float4 b4 = *(const float4*)(bi + t * 4);
    float4 o4;
    o4.x = (v.x - mu) * r * g4.x + b4.x;
    o4.y = (v.y - mu) * r * g4.y + b4.y;
    o4.z = (v.z - mu) * r * g4.z + b4.z;
    o4.w = (v.w - mu) * r * g4.w + b4.w;
    const size_t off = (size_t)row * DMODEL + t * 4;
    ((__half2*)(y + off))[0] = __floats2half2_rn(o4.x, o4.y);
    ((__half2*)(y + off))[1] = __floats2half2_rn(o4.z, o4.w);
}

// ---------------------------------------------------------------------------
// HMMA fp16 GEMM (R14 measured-best, unchanged): C = A @ W^T, fp32 accum.
//   EPI 0: none | 1: +res | 2: +bias,GELU | 3: +bias+res
//   OUTMODE 0: fp32 C | 2: single fp16 Ch
//   QSCALE 1: multiply cols [0,1024) by QKSCALE before store
// CTA tile 128x256, 512 threads = 16 warps (4x4), warp tile 32x64, BK=64,
// 3-stage cp.async ring, one barrier per k-tile.
// ---------------------------------------------------------------------------
#define GH_ROWB  144
#define GH_A_ARR (128 * GH_ROWB)
#define GH_B_ARR (256 * GH_ROWB)
#define GH_STAGE (GH_A_ARR + GH_B_ARR)     // 55296
#define GH_SMEM  (3 * GH_STAGE)            // 165888

template <int EPI, int OUTMODE, int QSCALE>
__global__ __launch_bounds__(512, 1)
void gemm_hmma(const __half* __restrict__ Ah, const __half* __restrict__ Bh,
               float* __restrict__ C, __half* __restrict__ Ch,
               int M, int N, int K,
               const float* __restrict__ bias, const float* __restrict__ res) {
    extern __shared__ char sm[];
    const uint32_t sb = smem_u32(sm);
    const int tid = threadIdx.x;
    const int lane = tid & 31, wid = tid >> 5;
    const int warp_m = wid >> 2, warp_n = wid & 3;   // 4 x 4
    const int bm = blockIdx.y * 128, bn = blockIdx.x * 256;
    const int NT = K >> 6;   // K tiles of 64

    auto load_stage = [&](int st, int kt) {
        const int k0 = kt * 64;
        const uint32_t so = sb + st * GH_STAGE;
#pragma unroll
        for (int i = 0; i < 2; i++) {                 // A: 128 rows x 8 kc
            const int idx = tid + i * 512;
            const int r = idx >> 3, kc = idx & 7;
            CP_ASYNC16(so + r * GH_ROWB + kc * 16,
                       Ah + (size_t)(bm + r) * K + k0 + kc * 8);
        }
#pragma unroll
        for (int i = 0; i < 4; i++) {                 // B: 256 rows x 8 kc
            const int idx = tid + i * 512;
            const int r = idx >> 3, kc = idx & 7;
            CP_ASYNC16(so + GH_A_ARR + r * GH_ROWB + kc * 16,
                       Bh + (size_t)(bn + r) * K + k0 + kc * 8);
        }
    };

    load_stage(0, 0); CP_COMMIT();

    float acc[2][8][4];
#pragma unroll
    for (int a = 0; a < 2; a++)
#pragma unroll
        for (int b = 0; b < 8; b++)
#pragma unroll
            for (int c = 0; c < 4; c++) acc[a][b][c] = 0.f;

    for (int kt = 0; kt < NT; kt++) {
        if (kt + 1 < NT) load_stage((kt + 1) % 3, kt + 1);
        CP_COMMIT();
        CP_WAIT1();
        __syncthreads();

        const uint32_t s0 = sb + (kt % 3) * GH_STAGE;
#pragma unroll
        for (int kh = 0; kh < 4; kh++) {
            uint32_t a_f[2][4], b_f[4][4];
#pragma unroll
            for (int mt = 0; mt < 2; mt++) {
                const int row = warp_m * 32 + mt * 16 + (lane & 15);
                LDSM_X4(a_f[mt], s0 + row * GH_ROWB + kh * 32 + (lane >> 4) * 16);
            }
#pragma unroll
            for (int nt = 0; nt < 4; nt++) {
                const int row = warp_n * 64 + nt * 16 + (lane & 7) + ((lane >> 4) << 3);
                LDSM_X4(b_f[nt], s0 + GH_A_ARR + row * GH_ROWB + kh * 32 +
                                 ((lane >> 3) & 1) * 16);
            }
#pragma unroll
            for (int mt = 0; mt < 2; mt++)
#pragma unroll
                for (int j = 0; j < 8; j++)
                    MMA16816(acc[mt][j], a_f[mt],
                             b_f[j >> 1][(j & 1) * 2], b_f[j >> 1][(j & 1) * 2 + 1]);
        }
    }

    const int gq = lane >> 2, tq = lane & 3;
#pragma unroll
    for (int mt = 0; mt < 2; mt++) {
#pragma unroll
        for (int j = 0; j < 8; j++) {
            const int col = bn + warp_n * 64 + j * 8 + tq * 2;
            float2 bb = make_float2(0.f, 0.f);
            if (EPI == 2 || EPI == 3) bb = *(const float2*)&bias[col];
#pragma unroll
            for (int rr = 0; rr < 2; rr++) {
                const int row = bm + warp_m * 32 + mt * 16 + gq + rr * 8;
                float vx = acc[mt][j][rr * 2 + 0];
                float vy = acc[mt][j][rr * 2 + 1];
                if (EPI == 2 || EPI == 3) { vx += bb.x; vy += bb.y; }
                if (EPI == 2) { vx = gelu_exact(vx); vy = gelu_exact(vy); }
                if (EPI == 1 || EPI == 3) {
                    const float2 rv = *(const float2*)&res[(size_t)row * N + col];
                    vx += rv.x; vy += rv.y;
                }
                if (QSCALE && col < DMODEL) { vx *= QKSCALE; vy *= QKSCALE; }
                if (OUTMODE == 2) {
                    *(__half2*)&Ch[(size_t)row * N + col] = __floats2half2_rn(vx, vy);
                } else {
                    *(float2*)&C[(size_t)row * N + col] = make_float2(vx, vy);
                }
            }
        }
    }
}

// ---------------------------------------------------------------------------
// HMMA flash attention (R14 structure + deferred l-reduce).
// Grid (T/128, H, B), 128 threads = 4 warps; each warp owns 32 q-rows
// (2 row-groups, V/K fragments shared across them).
// Q pre-scaled by log2e/sqrt(dh) -> softmax in exp2 domain.
// K/V 64x64 tiles, 3-stage cp.async ring, prefetch distance 2,
// one barrier per kv-tile. 2 CTAs/SM.
// Softmax SUM reduce deferred to epilogue (per-lane partial l; alpha is
// row-uniform, so the recurrence is linear in the lane partials).
// ---------------------------------------------------------------------------
#define AQ_S 72
#define ATT_Q     0
#define ATT_K(s)  (9216 + (s) * 4608)
#define ATT_V(s)  (23040 + (s) * 4608)
#define ATT_SMEM  (36864 * 2)          // 73728 B

__global__ __launch_bounds__(128, 2)
void attn_hmma(const __half* __restrict__ qkv, __half* __restrict__ ao) {
    extern __shared__ __half sh[];
    const uint32_t sb = smem_u32(sh);
    const int tid = threadIdx.x;
    const int lane = tid & 31, w = tid >> 5;
    const int b = blockIdx.z, h = blockIdx.y, qt = blockIdx.x;
    const int hoff = h * DHEAD;
    const int rowbase = b * TSEQ + qt * 128;

    // Load Q tile (128 rows x 64 halfs)
#pragma unroll
    for (int p = 0; p < 8; p++) {
        const int idx = tid + p * 128;
        const int r = idx >> 3, c8 = idx & 7;
        *(uint4*)(sh + ATT_Q + r * AQ_S + c8 * 8) =
            *(const uint4*)(qkv + (size_t)(rowbase + r) * 3072 + hoff + c8 * 8);
    }

    auto load_kv = [&](int st, int kt) {
        const int kvbase = b * TSEQ + kt * 64;
#pragma unroll
        for (int p = 0; p < 4; p++) {
            const int idx = tid + p * 128;
            const int r = idx >> 3, c8 = idx & 7;
            const __half* gk = qkv + (size_t)(kvbase + r) * 3072 + 1024 + hoff + c8 * 8;
            CP_ASYNC16(sb + 2 * (ATT_K(st) + r * AQ_S + c8 * 8), gk);
            CP_ASYNC16(sb + 2 * (ATT_V(st) + r * AQ_S + c8 * 8), gk + 1024);
        }
    };

    load_kv(0, 0); CP_COMMIT();
    load_kv(1, 1); CP_COMMIT();
    __syncthreads();   // Q visibility (plain stores) before ldsm preload

    // Preload Q A-fragments: 2 row-groups x 4 k-steps
    uint32_t qa[2][4][4];
    const int m0 = w * 32;
#pragma unroll
    for (int mt = 0; mt < 2; mt++)
#pragma unroll
        for (int kk = 0; kk < 4; kk++) {
            const uint32_t ad = sb + 2 * (ATT_Q + (m0 + mt * 16 + (lane & 15)) * AQ_S +
                                          kk * 16 + (lane >> 4) * 8);
            LDSM_X4(qa[mt][kk], ad);
        }

    float m_[2][2], l_[2][2];   // l_ = per-lane partial sums (reduced at end)
    float o[2][8][4];
#pragma unroll
    for (int mt = 0; mt < 2; mt++) {
        m_[mt][0] = -1e30f; m_[mt][1] = -1e30f;
        l_[mt][0] = 0.f;    l_[mt][1] = 0.f;
#pragma unroll
        for (int n = 0; n < 8; n++)
#pragma unroll
            for (int j = 0; j < 4; j++) o[mt][n][j] = 0.f;
    }

    const int NT = TSEQ / 64;
    for (int kt = 0; kt < NT; kt++) {
        CP_WAIT1();
        __syncthreads();
        if (kt + 2 < NT) load_kv((kt + 2) % 3, kt + 2);
        CP_COMMIT();
        const int s = kt % 3;

        // ---- S = Q K^T (log2-domain scores) ----
        float c[2][8][4];
#pragma unroll
        for (int mt = 0; mt < 2; mt++)
#pragma unroll
            for (int n = 0; n < 8; n++)
#pragma unroll
                for (int j = 0; j < 4; j++) c[mt][n][j] = 0.f;

#pragma unroll
        for (int kk2 = 0; kk2 < 2; kk2++) {
#pragma unroll
            for (int n = 0; n < 8; n++) {
                uint32_t bf[4];
                const uint32_t ad = sb + 2 * (ATT_K(s) + (n * 8 + (lane & 7)) * AQ_S +
                                              kk2 * 32 + (lane >> 3) * 8);
                LDSM_X4(bf, ad);
#pragma unroll
                for (int mt = 0; mt < 2; mt++) {
                    MMA16816(c[mt][n], qa[mt][2 * kk2], bf[0], bf[1]);
                    MMA16816(c[mt][n], qa[mt][2 * kk2 + 1], bf[2], bf[3]);
                }
            }
        }

        // ---- online softmax per row-group (exp2 domain, deferred sum) ----
        uint32_t u01[2][8], u23[2][8];
#pragma unroll
        for (int mt = 0; mt < 2; mt++) {
            float tm0 = -1e30f, tm1 = -1e30f;
#pragma unroll
            for (int n = 0; n < 8; n++) {
                tm0 = fmaxf(tm0, fmaxf(c[mt][n][0], c[mt][n][1]));
                tm1 = fmaxf(tm1, fmaxf(c[mt][n][2], c[mt][n][3]));
            }
#pragma unroll
            for (int ofs = 1; ofs <= 2; ofs <<= 1) {
                tm0 = fmaxf(tm0, __shfl_xor_sync(0xffffffffu, tm0, ofs));
                tm1 = fmaxf(tm1, __shfl_xor_sync(0xffffffffu, tm1, ofs));
            }
            const float mn0 = fmaxf(m_[mt][0], tm0), mn1 = fmaxf(m_[mt][1], tm1);
            const float al0 = ex2f(m_[mt][0] - mn0), al1 = ex2f(m_[mt][1] - mn1);
            m_[mt][0] = mn0; m_[mt][1] = mn1;

            float rs0 = 0.f, rs1 = 0.f;
#pragma unroll
            for (int n = 0; n < 8; n++) {
                const float p0 = ex2f(c[mt][n][0] - mn0);
                const float p1 = ex2f(c[mt][n][1] - mn0);
                const float p2 = ex2f(c[mt][n][2] - mn1);
                const float p3 = ex2f(c[mt][n][3] - mn1);
                rs0 += p0 + p1; rs1 += p2 + p3;
                const __half2 h01 = __floats2half2_rn(p0, p1);
                const __half2 h23 = __floats2half2_rn(p2, p3);
                u01[mt][n] = *(const uint32_t*)&h01;
                u23[mt][n] = *(const uint32_t*)&h23;
            }
            l_[mt][0] = l_[mt][0] * al0 + rs0;   // per-lane partial
            l_[mt][1] = l_[mt][1] * al1 + rs1;
#pragma unroll
            for (int n = 0; n < 8; n++) {
                o[mt][n][0] *= al0; o[mt][n][1] *= al0;
                o[mt][n][2] *= al1; o[mt][n][3] *= al1;
            }
        }

        // ---- O += P V (V fragments shared across row-groups) ----
#pragma unroll
        for (int kk = 0; kk < 4; kk++) {
            uint32_t au0[4] = {u01[0][2 * kk], u23[0][2 * kk],
                               u01[0][2 * kk + 1], u23[0][2 * kk + 1]};
            uint32_t au1[4] = {u01[1][2 * kk], u23[1][2 * kk],
                               u01[1][2 * kk + 1], u23[1][2 * kk + 1]};
#pragma unroll
            for (int n2 = 0; n2 < 4; n2++) {
                uint32_t bf[4];
                const uint32_t ad = sb + 2 * (ATT_V(s) + (kk * 16 + (lane & 15)) * AQ_S +
                                              n2 * 16 + (lane >> 4) * 8);
                LDSM_X4_T(bf, ad);
                MMA16816(o[0][2 * n2], au0, bf[0], bf[1]);
                MMA16816(o[0][2 * n2 + 1], au0, bf[2], bf[3]);
                MMA16816(o[1][2 * n2], au1, bf[0], bf[1]);
                MMA16816(o[1][2 * n2 + 1], au1, bf[2], bf[3]);
            }
        }
    }

    // ---- epilogue: reduce deferred l across the 4 lanes of each row ----
#pragma unroll
    for (int mt = 0; mt < 2; mt++)
#pragma unroll
        for (int ofs = 1; ofs <= 2; ofs <<= 1) {
            l_[mt][0] += __shfl_xor_sync(0xffffffffu, l_[mt][0], ofs);
            l_[mt][1] += __shfl_xor_sync(0xffffffffu, l_[mt][1], ofs);
        }
    const int r0 = lane >> 2, tq = lane & 3;
#pragma unroll
    for (int mt = 0; mt < 2; mt++) {
        const float inv0 = 1.0f / l_[mt][0], inv1 = 1.0f / l_[mt][1];
        const int grow0 = rowbase + m0 + mt * 16 + r0, grow1 = grow0 + 8;
#pragma unroll
        for (int n = 0; n < 8; n++) {
            const int col = hoff + n * 8 + tq * 2;
            *(__half2*)&ao[(size_t)grow0 * DMODEL + col] =
                __floats2half2_rn(o[mt][n][0] * inv0, o[mt][n][1] * inv0);
            *(__half2*)&ao[(size_t)grow1 * DMODEL + col] =
                __floats2half2_rn(o[mt][n][2] * inv1, o[mt][n][3] * inv1);
        }
    }
}

// ---------------------------------------------------------------------------
// Launcher
// ---------------------------------------------------------------------------
extern "C" void kernel_launch(void* const* d_in, const int* in_sizes, int n_in,
                              void* d_out, int out_size) {
    const float* x     = (const float*)d_in[0];
    const float* ln1_s = (const float*)d_in[1];
    const float* ln1_b = (const float*)d_in[2];
    const float* qkv_w = (const float*)d_in[3];
    const float* out_w = (const float*)d_in[4];
    const float* ln2_s = (const float*)d_in[5];
    const float* ln2_b = (const float*)d_in[6];
    const float* fc1_w = (const float*)d_in[7];
    const float* fc1_b = (const float*)d_in[8];
    const float* fc2_w = (const float*)d_in[9];
    const float* fc2_b = (const float*)d_in[10];
    float* out = (float*)d_out;

    float *x1_p;
    __half *qkvh, *act, *ff, *wq, *wo, *w1, *w2;
    cudaGetSymbolAddress((void**)&x1_p, g_x1);
    cudaGetSymbolAddress((void**)&qkvh, g_qkvh);
    cudaGetSymbolAddress((void**)&act, g_act);
    cudaGetSymbolAddress((void**)&ff, g_ff);
    cudaGetSymbolAddress((void**)&wq, g_wqkv);
    cudaGetSymbolAddress((void**)&wo, g_wout);
    cudaGetSymbolAddress((void**)&w1, g_wfc1);
    cudaGetSymbolAddress((void**)&w2, g_wfc2);

    cudaFuncSetAttribute(gemm_hmma<0, 2, 1>, cudaFuncAttributeMaxDynamicSharedMemorySize, GH_SMEM);
    cudaFuncSetAttribute(gemm_hmma<1, 0, 0>, cudaFuncAttributeMaxDynamicSharedMemorySize, GH_SMEM);
    cudaFuncSetAttribute(gemm_hmma<2, 2, 0>, cudaFuncAttributeMaxDynamicSharedMemorySize, GH_SMEM);
    cudaFuncSetAttribute(gemm_hmma<3, 0, 0>, cudaFuncAttributeMaxDynamicSharedMemorySize, GH_SMEM);
    cudaFuncSetAttribute(attn_hmma, cudaFuncAttributeMaxDynamicSharedMemorySize, ATT_SMEM);

    // 0) Weight prep: all four fp32 -> fp16 in ONE launch
    cvt4_kernel<<<N4_TOTAL / 256, 256>>>(qkv_w, out_w, fc1_w, fc2_w, wq, wo, w1, w2);

    // 1) LN1 -> fp16 activations
    ln_kernel<<<MROWS, 256>>>(x, ln1_s, ln1_b, act);

    // 2) QKV projection -> fp16 (Q pre-scaled by log2e/8)
    gemm_hmma<0, 2, 1><<<dim3(3 * DMODEL / 256, MROWS / 128), 512, GH_SMEM>>>(
        act, wq, nullptr, qkvh, MROWS, 3 * DMODEL, DMODEL, nullptr, nullptr);

    // 3) HMMA flash attention -> fp16 (128 threads, V-shared, 2 CTAs/SM)
    attn_hmma<<<dim3(TSEQ / 128, NHEAD, BATCH), 128, ATT_SMEM>>>(qkvh, act);

    // 4) Out projection + residual -> x1 fp32
    gemm_hmma<1, 0, 0><<<dim3(DMODEL / 256, MROWS / 128), 512, GH_SMEM>>>(
        act, wo, x1_p, nullptr, MROWS, DMODEL, DMODEL, nullptr, x);

    // 5) LN2 -> fp16 activations
    ln_kernel<<<MROWS, 256>>>(x1_p, ln2_s, ln2_b, act);

    // 6) FC1 + bias + GELU -> fp16
    gemm_hmma<2, 2, 0><<<dim3(DFF / 256, MROWS / 128), 512, GH_SMEM>>>(
        act, w1, nullptr, ff, MROWS, DFF, DMODEL, fc1_b, nullptr);

    // 7) FC2 + bias + residual -> out fp32
    gemm_hmma<3, 0, 0><<<dim3(DMODEL / 256, MROWS / 128), 512, GH_SMEM>>>(
        ff, w2, out, nullptr, MROWS, DMODEL, DFF, fc2_b, x1_p);
}

// round 17
// speedup vs baseline: 1.0215x; 1.0048x over previous
#include <cuda_runtime.h>
#include <cuda_fp16.h>
#include <math.h>
#include <stdint.h>

// Problem constants
#define BATCH 4
#define TSEQ 2048
#define DMODEL 1024
#define NHEAD 16
#define DHEAD 64
#define DFF 4096
#define MROWS (BATCH * TSEQ)   // 8192

// ---------------------------------------------------------------------------
// Scratch (device globals; no runtime allocation allowed)
// ---------------------------------------------------------------------------
__device__ float  g_x1[(size_t)MROWS * DMODEL];
__device__ __half g_qkvh[(size_t)MROWS * 3 * DMODEL];
__device__ __half g_act[(size_t)MROWS * DMODEL];
__device__ __half g_ff[(size_t)MROWS * DFF];
__device__ __half g_wqkv[(size_t)3 * DMODEL * DMODEL];
__device__ __half g_wout[(size_t)DMODEL * DMODEL];
__device__ __half g_wfc1[(size_t)DFF * DMODEL];
__device__ __half g_wfc2[(size_t)DMODEL * DFF];

// ---------------------------------------------------------------------------
// Helpers
// ---------------------------------------------------------------------------
__device__ __forceinline__ uint32_t smem_u32(const void* p) {
    uint32_t a;
    asm("{ .reg .u64 t; cvta.to.shared.u64 t, %1; cvt.u32.u64 %0, t; }"
        : "=r"(a) : "l"(p));
    return a;
}

__device__ __forceinline__ float ex2f(float x) {   // raw MUFU.EX2
    float r;
    asm("ex2.approx.f32 %0, %1;" : "=f"(r) : "f"(x));
    return r;
}

#define LDSM_X4(d, a)                                                        \
    asm volatile("ldmatrix.sync.aligned.m8n8.x4.shared.b16 "                 \
                 "{%0,%1,%2,%3}, [%4];"                                      \
                 : "=r"((d)[0]), "=r"((d)[1]), "=r"((d)[2]), "=r"((d)[3])    \
                 : "r"(a))

#define LDSM_X4_T(d, a)                                                      \
    asm volatile("ldmatrix.sync.aligned.m8n8.x4.trans.shared.b16 "           \
                 "{%0,%1,%2,%3}, [%4];"                                      \
                 : "=r"((d)[0]), "=r"((d)[1]), "=r"((d)[2]), "=r"((d)[3])    \
                 : "r"(a))

#define MMA16816(c, a, b0, b1)                                               \
    asm volatile("mma.sync.aligned.m16n8k16.row.col.f32.f16.f16.f32 "        \
                 "{%0,%1,%2,%3},{%4,%5,%6,%7},{%8,%9},{%0,%1,%2,%3};"        \
                 : "+f"((c)[0]), "+f"((c)[1]), "+f"((c)[2]), "+f"((c)[3])    \
                 : "r"((a)[0]), "r"((a)[1]), "r"((a)[2]), "r"((a)[3]),       \
                   "r"(b0), "r"(b1))

#define CP_ASYNC16(s, g) \
    asm volatile("cp.async.cg.shared.global [%0], [%1], 16;" :: "r"(s), "l"(g))
#define CP_COMMIT() asm volatile("cp.async.commit_group;")
#define CP_WAIT1()  asm volatile("cp.async.wait_group 1;")

__device__ __forceinline__ float gelu_exact(float x) {
    return 0.5f * x * (1.0f + erff(x * 0.70710678118654752f));
}

// Q pre-scale: (1/sqrt(64)) * log2(e) so softmax runs in exp2 domain
#define QKSCALE 0.18033688011112042f

// ---------------------------------------------------------------------------
// LayerNorm body (one block per row, 256 threads) -> single fp16
// ---------------------------------------------------------------------------
__device__ __forceinline__ void ln_body(const float* __restrict__ x,
                                        const float* __restrict__ sc,
                                        const float* __restrict__ bi,
                                        __half* __restrict__ y, int row) {
    const int t = threadIdx.x;
    const float4 v = *(const float4*)(x + (size_t)row * DMODEL + t * 4);
    float s = v.x + v.y + v.z + v.w;
    float s2 = v.x * v.x + v.y * v.y + v.z * v.z + v.w * v.w;
#pragma unroll
    for (int o = 16; o; o >>= 1) {
        s  += __shfl_xor_sync(0xffffffffu, s, o);
        s2 += __shfl_xor_sync(0xffffffffu, s2, o);
    }
    __shared__ float rs[8], rs2[8];
    if ((t & 31) == 0) { rs[t >> 5] = s; rs2[t >> 5] = s2; }
    __syncthreads();
    s = 0.f; s2 = 0.f;
#pragma unroll
    for (int i = 0; i < 8; i++) { s += rs[i]; s2 += rs2[i]; }
    const float mu = s * (1.0f / DMODEL);
    const float var = s2 * (1.0f / DMODEL) - mu * mu;
    const float r = rsqrtf(var + 1e-5f);
    const float4 g4 = *(const float4*)(sc + t * 4);
    const float4 b4 = *(const float4*)(bi + t * 4);
    float4 o4;
    o4.x = (v.x - mu) * r * g4.x + b4.x;
    o4.y = (v.y - mu) * r * g4.y + b4.y;
    o4.z = (v.z - mu) * r * g4.z + b4.z;
    o4.w = (v.w - mu) * r * g4.w + b4.w;
    const size_t off = (size_t)row * DMODEL + t * 4;
    ((__half2*)(y + off))[0] = __floats2half2_rn(o4.x, o4.y);
    ((__half2*)(y + off))[1] = __floats2half2_rn(o4.z, o4.w);
}

__global__ __launch_bounds__(256)
void ln_kernel(const float* __restrict__ x, const float* __restrict__ sc,
               const float* __restrict__ bi, __half* __restrict__ y) {
    ln_body(x, sc, bi, y, blockIdx.x);
}

// ---------------------------------------------------------------------------
// Fused prep: weight converts (4 tensors) + LN1, ONE launch.
// Blocks [0, N4_TOTAL/256): cvt; blocks [N4_TOTAL/256, +MROWS): LN1 rows.
// ---------------------------------------------------------------------------
#define N4_WQ (3 * DMODEL * DMODEL / 4)
#define N4_WO (DMODEL * DMODEL / 4)
#define N4_W1 (DFF * DMODEL / 4)
#define N4_W2 (DMODEL * DFF / 4)
#define N4_TOTAL (N4_WQ + N4_WO + N4_W1 + N4_W2)
#define NCVT_BLK (N4_TOTAL / 256)

__global__ __launch_bounds__(256)
void prep_kernel(const float* __restrict__ wq_in, const float* __restrict__ wo_in,
                 const float* __restrict__ w1_in, const float* __restrict__ w2_in,
                 __half* __restrict__ wq, __half* __restrict__ wo,
                 __half* __restrict__ w1, __half* __restrict__ w2,
                 const float* __restrict__ x, const float* __restrict__ ln1_s,
                 const float* __restrict__ ln1_b, __half* __restrict__ act) {
    if (blockIdx.x >= NCVT_BLK) {
        ln_body(x, ln1_s, ln1_b, act, blockIdx.x - NCVT_BLK);
        return;
    }
    int i = blockIdx.x * 256 + threadIdx.x;
    const float* in;
    __half* out;
    if (i < N4_WQ)                       { in = wq_in; out = wq; }
    else if ((i -= N4_WQ) < N4_WO)       { in = wo_in; out = wo; }
    else if ((i -= N4_WO) < N4_W1)       { in = w1_in; out = w1; }
    else { i -= N4_W1;                     in = w2_in; out = w2; }
    const float4 v = ((const float4*)in)[i];
    ((__half2*)out)[i * 2 + 0] = __floats2half2_rn(v.x, v.y);
    ((__half2*)out)[i * 2 + 1] = __floats2half2_rn(v.z, v.w);
}

// ---------------------------------------------------------------------------
// HMMA fp16 GEMM (R14 measured-best, unchanged): C = A @ W^T, fp32 accum.
//   EPI 0: none | 1: +res | 2: +bias,GELU | 3: +bias+res
//   OUTMODE 0: fp32 C | 2: single fp16 Ch
//   QSCALE 1: multiply cols [0,1024) by QKSCALE before store
// CTA tile 128x256, 512 threads = 16 warps (4x4), warp tile 32x64, BK=64,
// 3-stage cp.async ring, one barrier per k-tile.
// ---------------------------------------------------------------------------
#define GH_ROWB  144
#define GH_A_ARR (128 * GH_ROWB)
#define GH_B_ARR (256 * GH_ROWB)
#define GH_STAGE (GH_A_ARR + GH_B_ARR)     // 55296
#define GH_SMEM  (3 * GH_STAGE)            // 165888

template <int EPI, int OUTMODE, int QSCALE>
__global__ __launch_bounds__(512, 1)
void gemm_hmma(const __half* __restrict__ Ah, const __half* __restrict__ Bh,
               float* __restrict__ C, __half* __restrict__ Ch,
               int M, int N, int K,
               const float* __restrict__ bias, const float* __restrict__ res) {
    extern __shared__ char sm[];
    const uint32_t sb = smem_u32(sm);
    const int tid = threadIdx.x;
    const int lane = tid & 31, wid = tid >> 5;
    const int warp_m = wid >> 2, warp_n = wid & 3;   // 4 x 4
    const int bm = blockIdx.y * 128, bn = blockIdx.x * 256;
    const int NT = K >> 6;   // K tiles of 64

    auto load_stage = [&](int st, int kt) {
        const int k0 = kt * 64;
        const uint32_t so = sb + st * GH_STAGE;
#pragma unroll
        for (int i = 0; i < 2; i++) {                 // A: 128 rows x 8 kc
            const int idx = tid + i * 512;
            const int r = idx >> 3, kc = idx & 7;
            CP_ASYNC16(so + r * GH_ROWB + kc * 16,
                       Ah + (size_t)(bm + r) * K + k0 + kc * 8);
        }
#pragma unroll
        for (int i = 0; i < 4; i++) {                 // B: 256 rows x 8 kc
            const int idx = tid + i * 512;
            const int r = idx >> 3, kc = idx & 7;
            CP_ASYNC16(so + GH_A_ARR + r * GH_ROWB + kc * 16,
                       Bh + (size_t)(bn + r) * K + k0 + kc * 8);
        }
    };

    load_stage(0, 0); CP_COMMIT();

    float acc[2][8][4];
#pragma unroll
    for (int a = 0; a < 2; a++)
#pragma unroll
        for (int b = 0; b < 8; b++)
#pragma unroll
            for (int c = 0; c < 4; c++) acc[a][b][c] = 0.f;

    for (int kt = 0; kt < NT; kt++) {
        if (kt + 1 < NT) load_stage((kt + 1) % 3, kt + 1);
        CP_COMMIT();
        CP_WAIT1();
        __syncthreads();

        const uint32_t s0 = sb + (kt % 3) * GH_STAGE;
#pragma unroll
        for (int kh = 0; kh < 4; kh++) {
            uint32_t a_f[2][4], b_f[4][4];
#pragma unroll
            for (int mt = 0; mt < 2; mt++) {
                const int row = warp_m * 32 + mt * 16 + (lane & 15);
                LDSM_X4(a_f[mt], s0 + row * GH_ROWB + kh * 32 + (lane >> 4) * 16);
            }
#pragma unroll
            for (int nt = 0; nt < 4; nt++) {
                const int row = warp_n * 64 + nt * 16 + (lane & 7) + ((lane >> 4) << 3);
                LDSM_X4(b_f[nt], s0 + GH_A_ARR + row * GH_ROWB + kh * 32 +
                                 ((lane >> 3) & 1) * 16);
            }
#pragma unroll
            for (int mt = 0; mt < 2; mt++)
#pragma unroll
                for (int j = 0; j < 8; j++)
                    MMA16816(acc[mt][j], a_f[mt],
                             b_f[j >> 1][(j & 1) * 2], b_f[j >> 1][(j & 1) * 2 + 1]);
        }
    }

    const int gq = lane >> 2, tq = lane & 3;
#pragma unroll
    for (int mt = 0; mt < 2; mt++) {
#pragma unroll
        for (int j = 0; j < 8; j++) {
            const int col = bn + warp_n * 64 + j * 8 + tq * 2;
            float2 bb = make_float2(0.f, 0.f);
            if (EPI == 2 || EPI == 3) bb = *(const float2*)&bias[col];
#pragma unroll
            for (int rr = 0; rr < 2; rr++) {
                const int row = bm + warp_m * 32 + mt * 16 + gq + rr * 8;
                float vx = acc[mt][j][rr * 2 + 0];
                float vy = acc[mt][j][rr * 2 + 1];
                if (EPI == 2 || EPI == 3) { vx += bb.x; vy += bb.y; }
                if (EPI == 2) { vx = gelu_exact(vx); vy = gelu_exact(vy); }
                if (EPI == 1 || EPI == 3) {
                    const float2 rv = *(const float2*)&res[(size_t)row * N + col];
                    vx += rv.x; vy += rv.y;
                }
                if (QSCALE && col < DMODEL) { vx *= QKSCALE; vy *= QKSCALE; }
                if (OUTMODE == 2) {
                    *(__half2*)&Ch[(size_t)row * N + col] = __floats2half2_rn(vx, vy);
                } else {
                    *(float2*)&C[(size_t)row * N + col] = make_float2(vx, vy);
                }
            }
        }
    }
}

// ---------------------------------------------------------------------------
// HMMA flash attention (R14 exact, measured best 201.6 us).
// Grid (T/128, H, B), 128 threads = 4 warps; each warp owns 32 q-rows
// (2 row-groups, V/K fragments shared). Q pre-scaled by log2e/sqrt(dh);
// softmax in exp2 domain. 3-stage cp.async ring, prefetch distance 2,
// one barrier per kv-tile, 2 CTAs/SM.
// ---------------------------------------------------------------------------
#define AQ_S 72
#define ATT_Q     0
#define ATT_K(s)  (9216 + (s) * 4608)
#define ATT_V(s)  (23040 + (s) * 4608)
#define ATT_SMEM  (36864 * 2)          // 73728 B

__global__ __launch_bounds__(128, 2)
void attn_hmma(const __half* __restrict__ qkv, __half* __restrict__ ao) {
    extern __shared__ __half sh[];
    const uint32_t sb = smem_u32(sh);
    const int tid = threadIdx.x;
    const int lane = tid & 31, w = tid >> 5;
    const int b = blockIdx.z, h = blockIdx.y, qt = blockIdx.x;
    const int hoff = h * DHEAD;
    const int rowbase = b * TSEQ + qt * 128;

    // Load Q tile (128 rows x 64 halfs)
#pragma unroll
    for (int p = 0; p < 8; p++) {
        const int idx = tid + p * 128;
        const int r = idx >> 3, c8 = idx & 7;
        *(uint4*)(sh + ATT_Q + r * AQ_S + c8 * 8) =
            *(const uint4*)(qkv + (size_t)(rowbase + r) * 3072 + hoff + c8 * 8);
    }

    auto load_kv = [&](int st, int kt) {
        const int kvbase = b * TSEQ + kt * 64;
#pragma unroll
        for (int p = 0; p < 4; p++) {
            const int idx = tid + p * 128;
            const int r = idx >> 3, c8 = idx & 7;
            const __half* gk = qkv + (size_t)(kvbase + r) * 3072 + 1024 + hoff + c8 * 8;
            CP_ASYNC16(sb + 2 * (ATT_K(st) + r * AQ_S + c8 * 8), gk);
            CP_ASYNC16(sb + 2 * (ATT_V(st) + r * AQ_S + c8 * 8), gk + 1024);
        }
    };

    load_kv(0, 0); CP_COMMIT();
    load_kv(1, 1); CP_COMMIT();
    __syncthreads();   // Q visibility (plain stores) before ldsm preload

    // Preload Q A-fragments: 2 row-groups x 4 k-steps
    uint32_t qa[2][4][4];
    const int m0 = w * 32;
#pragma unroll
    for (int mt = 0; mt < 2; mt++)
#pragma unroll
        for (int kk = 0; kk < 4; kk++) {
            const uint32_t ad = sb + 2 * (ATT_Q + (m0 + mt * 16 + (lane & 15)) * AQ_S +
                                          kk * 16 + (lane >> 4) * 8);
            LDSM_X4(qa[mt][kk], ad);
        }

    float m_[2][2], l_[2][2];
    float o[2][8][4];
#pragma unroll
    for (int mt = 0; mt < 2; mt++) {
        m_[mt][0] = -1e30f; m_[mt][1] = -1e30f;
        l_[mt][0] = 0.f;    l_[mt][1] = 0.f;
#pragma unroll
        for (int n = 0; n < 8; n++)
#pragma unroll
            for (int j = 0; j < 4; j++) o[mt][n][j] = 0.f;
    }

    const int NT = TSEQ / 64;
    for (int kt = 0; kt < NT; kt++) {
        CP_WAIT1();
        __syncthreads();
        if (kt + 2 < NT) load_kv((kt + 2) % 3, kt + 2);
        CP_COMMIT();
        const int s = kt % 3;

        // ---- S = Q K^T (log2-domain scores) ----
        float c[2][8][4];
#pragma unroll
        for (int mt = 0; mt < 2; mt++)
#pragma unroll
            for (int n = 0; n < 8; n++)
#pragma unroll
                for (int j = 0; j < 4; j++) c[mt][n][j] = 0.f;

#pragma unroll
        for (int kk2 = 0; kk2 < 2; kk2++) {
#pragma unroll
            for (int n = 0; n < 8; n++) {
                uint32_t bf[4];
                const uint32_t ad = sb + 2 * (ATT_K(s) + (n * 8 + (lane & 7)) * AQ_S +
                                              kk2 * 32 + (lane >> 3) * 8);
                LDSM_X4(bf, ad);
#pragma unroll
                for (int mt = 0; mt < 2; mt++) {
                    MMA16816(c[mt][n], qa[mt][2 * kk2], bf[0], bf[1]);
                    MMA16816(c[mt][n], qa[mt][2 * kk2 + 1], bf[2], bf[3]);
                }
            }
        }

        // ---- online softmax per row-group (exp2 domain) ----
        uint32_t u01[2][8], u23[2][8];
#pragma unroll
        for (int mt = 0; mt < 2; mt++) {
            float tm0 = -1e30f, tm1 = -1e30f;
#pragma unroll
            for (int n = 0; n < 8; n++) {
                tm0 = fmaxf(tm0, fmaxf(c[mt][n][0], c[mt][n][1]));
                tm1 = fmaxf(tm1, fmaxf(c[mt][n][2], c[mt][n][3]));
            }
#pragma unroll
            for (int ofs = 1; ofs <= 2; ofs <<= 1) {
                tm0 = fmaxf(tm0, __shfl_xor_sync(0xffffffffu, tm0, ofs));
                tm1 = fmaxf(tm1, __shfl_xor_sync(0xffffffffu, tm1, ofs));
            }
            const float mn0 = fmaxf(m_[mt][0], tm0), mn1 = fmaxf(m_[mt][1], tm1);
            const float al0 = ex2f(m_[mt][0] - mn0), al1 = ex2f(m_[mt][1] - mn1);
            m_[mt][0] = mn0; m_[mt][1] = mn1;

            float rs0 = 0.f, rs1 = 0.f;
#pragma unroll
            for (int n = 0; n < 8; n++) {
                const float p0 = ex2f(c[mt][n][0] - mn0);
                const float p1 = ex2f(c[mt][n][1] - mn0);
                const float p2 = ex2f(c[mt][n][2] - mn1);
                const float p3 = ex2f(c[mt][n][3] - mn1);
                rs0 += p0 + p1; rs1 += p2 + p3;
                const __half2 h01 = __floats2half2_rn(p0, p1);
                const __half2 h23 = __floats2half2_rn(p2, p3);
                u01[mt][n] = *(const uint32_t*)&h01;
                u23[mt][n] = *(const uint32_t*)&h23;
            }
#pragma unroll
            for (int ofs = 1; ofs <= 2; ofs <<= 1) {
                rs0 += __shfl_xor_sync(0xffffffffu, rs0, ofs);
                rs1 += __shfl_xor_sync(0xffffffffu, rs1, ofs);
            }
            l_[mt][0] = l_[mt][0] * al0 + rs0;
            l_[mt][1] = l_[mt][1] * al1 + rs1;
#pragma unroll
            for (int n = 0; n < 8; n++) {
                o[mt][n][0] *= al0; o[mt][n][1] *= al0;
                o[mt][n][2] *= al1; o[mt][n][3] *= al1;
            }
        }

        // ---- O += P V (V fragments shared across row-groups) ----
#pragma unroll
        for (int kk = 0; kk < 4; kk++) {
            uint32_t au0[4] = {u01[0][2 * kk], u23[0][2 * kk],
                               u01[0][2 * kk + 1], u23[0][2 * kk + 1]};
            uint32_t au1[4] = {u01[1][2 * kk], u23[1][2 * kk],
                               u01[1][2 * kk + 1], u23[1][2 * kk + 1]};
#pragma unroll
            for (int n2 = 0; n2 < 4; n2++) {
                uint32_t bf[4];
                const uint32_t ad = sb + 2 * (ATT_V(s) + (kk * 16 + (lane & 15)) * AQ_S +
                                              n2 * 16 + (lane >> 4) * 8);
                LDSM_X4_T(bf, ad);
                MMA16816(o[0][2 * n2], au0, bf[0], bf[1]);
                MMA16816(o[0][2 * n2 + 1], au0, bf[2], bf[3]);
                MMA16816(o[1][2 * n2], au1, bf[0], bf[1]);
                MMA16816(o[1][2 * n2 + 1], au1, bf[2], bf[3]);
            }
        }
    }

    // ---- epilogue ----
    const int r0 = lane >> 2, tq = lane & 3;
#pragma unroll
    for (int mt = 0; mt < 2; mt++) {
        const float inv0 = 1.0f / l_[mt][0], inv1 = 1.0f / l_[mt][1];
        const int grow0 = rowbase + m0 + mt * 16 + r0, grow1 = grow0 + 8;
#pragma unroll
        for (int n = 0; n < 8; n++) {
            const int col = hoff + n * 8 + tq * 2;
            *(__half2*)&ao[(size_t)grow0 * DMODEL + col] =
                __floats2half2_rn(o[mt][n][0] * inv0, o[mt][n][1] * inv0);
            *(__half2*)&ao[(size_t)grow1 * DMODEL + col] =
                __floats2half2_rn(o[mt][n][2] * inv1, o[mt][n][3] * inv1);
        }
    }
}

// ---------------------------------------------------------------------------
// Launcher
// ---------------------------------------------------------------------------
extern "C" void kernel_launch(void* const* d_in, const int* in_sizes, int n_in,
                              void* d_out, int out_size) {
    const float* x     = (const float*)d_in[0];
    const float* ln1_s = (const float*)d_in[1];
    const float* ln1_b = (const float*)d_in[2];
    const float* qkv_w = (const float*)d_in[3];
    const float* out_w = (const float*)d_in[4];
    const float* ln2_s = (const float*)d_in[5];
    const float* ln2_b = (const float*)d_in[6];
    const float* fc1_w = (const float*)d_in[7];
    const float* fc1_b = (const float*)d_in[8];
    const float* fc2_w = (const float*)d_in[9];
    const float* fc2_b = (const float*)d_in[10];
    float* out = (float*)d_out;

    float *x1_p;
    __half *qkvh, *act, *ff, *wq, *wo, *w1, *w2;
    cudaGetSymbolAddress((void**)&x1_p, g_x1);
    cudaGetSymbolAddress((void**)&qkvh, g_qkvh);
    cudaGetSymbolAddress((void**)&act, g_act);
    cudaGetSymbolAddress((void**)&ff, g_ff);
    cudaGetSymbolAddress((void**)&wq, g_wqkv);
    cudaGetSymbolAddress((void**)&wo, g_wout);
    cudaGetSymbolAddress((void**)&w1, g_wfc1);
    cudaGetSymbolAddress((void**)&w2, g_wfc2);

    cudaFuncSetAttribute(gemm_hmma<0, 2, 1>, cudaFuncAttributeMaxDynamicSharedMemorySize, GH_SMEM);
    cudaFuncSetAttribute(gemm_hmma<1, 0, 0>, cudaFuncAttributeMaxDynamicSharedMemorySize, GH_SMEM);
    cudaFuncSetAttribute(gemm_hmma<2, 2, 0>, cudaFuncAttributeMaxDynamicSharedMemorySize, GH_SMEM);
    cudaFuncSetAttribute(gemm_hmma<3, 0, 0>, cudaFuncAttributeMaxDynamicSharedMemorySize, GH_SMEM);
    cudaFuncSetAttribute(attn_hmma, cudaFuncAttributeMaxDynamicSharedMemorySize, ATT_SMEM);

    // 0) Fused prep: weight converts + LN1 in ONE launch
    prep_kernel<<<NCVT_BLK + MROWS, 256>>>(qkv_w, out_w, fc1_w, fc2_w,
                                           wq, wo, w1, w2,
                                           x, ln1_s, ln1_b, act);

    // 1) QKV projection -> fp16 (Q pre-scaled by log2e/8)
    gemm_hmma<0, 2, 1><<<dim3(3 * DMODEL / 256, MROWS / 128), 512, GH_SMEM>>>(
        act, wq, nullptr, qkvh, MROWS, 3 * DMODEL, DMODEL, nullptr, nullptr);

    // 2) HMMA flash attention -> fp16
    attn_hmma<<<dim3(TSEQ / 128, NHEAD, BATCH), 128, ATT_SMEM>>>(qkvh, act);

    // 3) Out projection + residual -> x1 fp32
    gemm_hmma<1, 0, 0><<<dim3(DMODEL / 256, MROWS / 128), 512, GH_SMEM>>>(
        act, wo, x1_p, nullptr, MROWS, DMODEL, DMODEL, nullptr, x);

    // 4) LN2 -> fp16 activations
    ln_kernel<<<MROWS, 256>>>(x1_p, ln2_s, ln2_b, act);

    // 5) FC1 + bias + GELU -> fp16
    gemm_hmma<2, 2, 0><<<dim3(DFF / 256, MROWS / 128), 512, GH_SMEM>>>(
        act, w1, nullptr, ff, MROWS, DFF, DMODEL, fc1_b, nullptr);

    // 6) FC2 + bias + residual -> out fp32
    gemm_hmma<3, 0, 0><<<dim3(DMODEL / 256, MROWS / 128), 512, GH_SMEM>>>(
        ff, w2, out, nullptr, MROWS, DMODEL, DFF, fc2_b, x1_p);
}